// round 17
// baseline (speedup 1.0000x reference)
#include <cuda_runtime.h>
#include <math.h>

#define NN4     (1024 * 1024 / 4)
#define TPB     256
#define NBLK    256              /* 256 blocks x 256 threads x 4 rows = grid */
#define NCYC    4
#define NGRP    16               /* barrier tree: 16 groups of 16 blocks */
#define GSZ     16

// ---------------- device scratch (allocations forbidden) --------------------
__device__ float4 g_S[16][NN4];    // Chebyshev basis s_0..s_15
__device__ float  g_part[33][NBLK];
__device__ unsigned g_cntGrp[NGRP][32];   // arrival counters, 128B apart
__device__ unsigned g_cntRoot;
__device__ volatile unsigned g_gen;

// ---------------- helpers ------------------------------------------------------
__device__ __forceinline__ float4 ns5(float4 C, float L, float R, float4 U, float4 D) {
    float4 n;
    n.x = L   + C.y + U.x + D.x;
    n.y = C.x + C.z + U.y + D.y;
    n.z = C.y + C.w + U.z + D.z;
    n.w = C.z + R   + U.w + D.w;
    return n;
}

// laterals for a row whose values exist in global u4 (shfl + edge-lane loads)
__device__ __forceinline__ void latG(const float4* __restrict__ u4, float4 C,
                                     int li, int ri, int lane, float& L, float& R) {
    L = __shfl_up_sync(0xffffffffu, C.w, 1);
    R = __shfl_down_sync(0xffffffffu, C.x, 1);
    if (lane == 0)  L = ((const float*)u4)[li];
    if (lane == 31) R = ((const float*)u4)[ri];
}

__device__ __forceinline__ float dot4(float4 a, float4 b) {
    return a.x * b.x + a.y * b.y + a.z * b.z + a.w * b.w;
}

__device__ __forceinline__ float4 sub_half_ns(float4 NS, float4 P) { // -NS/2 - P
    float4 r;
    r.x = -0.5f * NS.x - P.x; r.y = -0.5f * NS.y - P.y;
    r.z = -0.5f * NS.z - P.z; r.w = -0.5f * NS.w - P.w;
    return r;
}

__device__ __forceinline__ float4 quarter_neg(float4 NS) {           // -NS/4
    float4 r;
    r.x = -0.25f * NS.x; r.y = -0.25f * NS.y;
    r.z = -0.25f * NS.z; r.w = -0.25f * NS.w;
    return r;
}

__device__ __forceinline__ float warpSum(float v) {
#pragma unroll
    for (int o = 16; o > 0; o >>= 1) v += __shfl_down_sync(0xffffffffu, v, o);
    return v;
}

// ---------------- the persistent kernel ------------------------------------------
__global__ void __launch_bounds__(TPB, 2) k_all(const float4* __restrict__ b,
                                                const float4* __restrict__ guess,
                                                float4* __restrict__ out) {
    int q = blockIdx.x, col = threadIdx.x;
    int lane = col & 31, warp = col >> 5, t = col;
    int grp = q >> 4;
    int r0 = q << 2;
    int cl = ((col << 2) - 1) & 1023, cr = ((col << 2) + 4) & 1023;

    auto RO = [&](int d) { return (r0 + d) & 1023; };
    auto I4 = [&](int d) { return (RO(d) << 8) | col; };
    auto LI = [&](int d) { return (RO(d) << 10) | cl; };
    auto RI = [&](int d) { return (RO(d) << 10) | cr; };

    __shared__ float4 xb[8][TPB];                 // lateral-exchange buffer
    __shared__ float  sred[9][TPB / 32];
    __shared__ float  smu[33];
    __shared__ double mu[33];
    __shared__ double M[17][17];
    __shared__ double W[17][16];
    __shared__ double G[16][16], sf[16], rhs[16];
    __shared__ float  cs[16], ds[17];
    __shared__ unsigned sGen;

    // two-level tree barrier: 16 groups x 16 arrivals (parallel L2 lines)
    auto barArrive = [&]() {
        __syncthreads();
        if (t == 0) {
            __threadfence();
            unsigned g = g_gen;
            sGen = g;
            if (atomicAdd(&g_cntGrp[grp][0], 1u) == (unsigned)(GSZ - 1)) {
                g_cntGrp[grp][0] = 0u;
                __threadfence();
                if (atomicAdd(&g_cntRoot, 1u) == (unsigned)(NGRP - 1)) {
                    g_cntRoot = 0u;
                    __threadfence();
                    g_gen = g + 1u;
                }
            }
        }
        __syncthreads();
    };
    auto barWait = [&]() {
        if (t == 0) {
            unsigned g = sGen;
            while (g_gen == g) { }
            __threadfence();
        }
        __syncthreads();
    };

    // x register-resident (cold; ptxas may spill - touched once per cycle)
    float4 x[4];
#pragma unroll
    for (int k = 0; k < 4; k++) x[k] = guess[I4(k)];

    // ---- cycle-0 residual: s_0 = b - A(guess) ----
    float4 s[4], p[4];
    {
        float4 XU = guess[I4(-1)], XD = guess[I4(4)];
        float Lx, Rx;
#pragma unroll
        for (int k = 0; k < 4; k++) {
            latG(guess, x[k], LI(k), RI(k), lane, Lx, Rx);
            float4 up = (k == 0) ? XU : x[k - 1];
            float4 dn = (k == 3) ? XD : x[k + 1];
            float4 NS = ns5(x[k], Lx, Rx, up, dn);
            float4 bb = b[I4(k)];
            float4 r;
            r.x = bb.x - (4.3f * x[k].x - NS.x);
            r.y = bb.y - (4.3f * x[k].y - NS.y);
            r.z = bb.z - (4.3f * x[k].z - NS.z);
            r.w = bb.w - (4.3f * x[k].w - NS.w);
            s[k] = r;
            g_S[0][I4(k)] = r;
        }
    }
    barArrive(); barWait();

    for (int c = 0; c < NCYC; c++) {
        // ---- 4 quad-steps: each computes s_{i+1..i+4} under ONE barrier ----
        for (int jj = 0; jj < 4; jj++) {
            int i = 4 * jj;
            const float4* __restrict__ Si = g_S[i];

            // s_i rows d=-4..7 : owned from regs, halo from global
            float4 S[12];
#pragma unroll
            for (int k = 0; k < 4; k++) S[k + 4] = s[k];
            S[0]  = Si[I4(-4)]; S[1]  = Si[I4(-3)];
            S[2]  = Si[I4(-2)]; S[3]  = Si[I4(-1)];
            S[8]  = Si[I4(4)];  S[9]  = Si[I4(5)];
            S[10] = Si[I4(6)];  S[11] = Si[I4(7)];

            // s_{i-1} rows d=-3..6 (PL); L1 computed in place
            float4 PL[10];
            if (i > 0) {
                const float4* __restrict__ Sm = g_S[i - 1];
#pragma unroll
                for (int k = 0; k < 4; k++) PL[k + 3] = p[k];
                PL[0] = Sm[I4(-3)]; PL[1] = Sm[I4(-2)]; PL[2] = Sm[I4(-1)];
                PL[7] = Sm[I4(4)];  PL[8] = Sm[I4(5)];  PL[9] = Sm[I4(6)];
            }

            // ---- level 1: s_{i+1} rows d=-3..6 ----
#pragma unroll
            for (int d = -3; d <= 6; d++) {
                float L, R;
                latG(Si, S[d + 4], LI(d), RI(d), lane, L, R);
                float4 NS = ns5(S[d + 4], L, R, S[d + 3], S[d + 5]);
                PL[d + 3] = (i == 0) ? quarter_neg(NS) : sub_half_ns(NS, PL[d + 3]);
            }
            float aI = 0.f, bI = 0.f;
#pragma unroll
            for (int k = 0; k < 4; k++) {
                aI += dot4(S[k + 4], S[k + 4]);
                bI += dot4(S[k + 4], PL[k + 3]);
            }
#pragma unroll
            for (int k = 0; k < 4; k++) g_S[i + 1][I4(k)] = PL[k + 3];

            // exchange L1 rows d=-2..5
#pragma unroll
            for (int d = -2; d <= 5; d++) xb[d + 2][col] = PL[d + 3];
            __syncthreads();
            int colL = (col + 255) & 255, colR = (col + 1) & 255;

            // ---- level 2: s_{i+2} rows d=-2..5 ----
            float4 L2a[8];
#pragma unroll
            for (int d = -2; d <= 5; d++) {
                float L = xb[d + 2][colL].w;
                float R = xb[d + 2][colR].x;
                float4 NS = ns5(PL[d + 3], L, R, PL[d + 2], PL[d + 4]);
                L2a[d + 2] = sub_half_ns(NS, S[d + 4]);
            }
            float aI1 = 0.f, bI1 = 0.f;
#pragma unroll
            for (int k = 0; k < 4; k++) {
                aI1 += dot4(PL[k + 3], PL[k + 3]);
                bI1 += dot4(PL[k + 3], L2a[k + 2]);
            }
#pragma unroll
            for (int k = 0; k < 4; k++) g_S[i + 2][I4(k)] = L2a[k + 2];

            __syncthreads();
#pragma unroll
            for (int d = -1; d <= 4; d++) xb[d + 1][col] = L2a[d + 2];
            __syncthreads();

            // ---- level 3: s_{i+3} rows d=-1..4 ----
            float4 L3a[6];
#pragma unroll
            for (int d = -1; d <= 4; d++) {
                float L = xb[d + 1][colL].w;
                float R = xb[d + 1][colR].x;
                float4 NS = ns5(L2a[d + 2], L, R, L2a[d + 1], L2a[d + 3]);
                L3a[d + 1] = sub_half_ns(NS, PL[d + 3]);
            }
            float aI2 = 0.f, bI2 = 0.f;
#pragma unroll
            for (int k = 0; k < 4; k++) {
                aI2 += dot4(L2a[k + 2], L2a[k + 2]);
                bI2 += dot4(L2a[k + 2], L3a[k + 1]);
            }
#pragma unroll
            for (int k = 0; k < 4; k++) g_S[i + 3][I4(k)] = L3a[k + 1];

            __syncthreads();
#pragma unroll
            for (int d = 0; d <= 3; d++) xb[d][col] = L3a[d + 1];
            __syncthreads();

            // ---- level 4: s_{i+4} rows d=0..3 ----
            float4 L4a[4];
#pragma unroll
            for (int d = 0; d <= 3; d++) {
                float L = xb[d][colL].w;
                float R = xb[d][colR].x;
                float4 NS = ns5(L3a[d + 1], L, R, L3a[d], L3a[d + 2]);
                L4a[d] = sub_half_ns(NS, L2a[d + 2]);
            }
            float aI3 = 0.f, bI3 = 0.f, a16 = 0.f;
#pragma unroll
            for (int k = 0; k < 4; k++) {
                aI3 += dot4(L3a[k + 1], L3a[k + 1]);
                bI3 += dot4(L3a[k + 1], L4a[k]);
            }
            if (jj == 3) {
#pragma unroll
                for (int k = 0; k < 4; k++) a16 += dot4(L4a[k], L4a[k]);
            } else {
#pragma unroll
                for (int k = 0; k < 4; k++) g_S[i + 4][I4(k)] = L4a[k];
            }

            // ---- reductions: overlap with barrier propagation where legal ----
            if (jj == 3) {
                // partials must be visible at release -> write BEFORE arrive
                float v;
                v = warpSum(aI);  if (lane == 0) sred[0][warp] = v;
                v = warpSum(bI);  if (lane == 0) sred[1][warp] = v;
                v = warpSum(aI1); if (lane == 0) sred[2][warp] = v;
                v = warpSum(bI1); if (lane == 0) sred[3][warp] = v;
                v = warpSum(aI2); if (lane == 0) sred[4][warp] = v;
                v = warpSum(bI2); if (lane == 0) sred[5][warp] = v;
                v = warpSum(aI3); if (lane == 0) sred[6][warp] = v;
                v = warpSum(bI3); if (lane == 0) sred[7][warp] = v;
                v = warpSum(a16); if (lane == 0) sred[8][warp] = v;
                __syncthreads();
                if (t < 9) {
                    float sum = 0.f;
#pragma unroll
                    for (int w = 0; w < TPB / 32; w++) sum += sred[t][w];
                    g_part[(t == 8) ? 32 : 24 + t][q] = sum;
                }
                barArrive();
            } else {
                barArrive();                 // stores visible; dots run while waiting
                float v;
                v = warpSum(aI);  if (lane == 0) sred[0][warp] = v;
                v = warpSum(bI);  if (lane == 0) sred[1][warp] = v;
                v = warpSum(aI1); if (lane == 0) sred[2][warp] = v;
                v = warpSum(bI1); if (lane == 0) sred[3][warp] = v;
                v = warpSum(aI2); if (lane == 0) sred[4][warp] = v;
                v = warpSum(bI2); if (lane == 0) sred[5][warp] = v;
                v = warpSum(aI3); if (lane == 0) sred[6][warp] = v;
                v = warpSum(bI3); if (lane == 0) sred[7][warp] = v;
                __syncthreads();
                if (t < 8) {
                    float sum = 0.f;
#pragma unroll
                    for (int w = 0; w < TPB / 32; w++) sum += sred[t][w];
                    g_part[8 * jj + t][q] = sum;   // consumed only after jj==3 barrier
                }
            }
#pragma unroll
            for (int k = 0; k < 4; k++) { p[k] = L3a[k + 1]; s[k] = L4a[k]; }
            barWait();
        }
        // registers now: p = s_15, s = s_16

        // ---- every block: reduce 33 moments + fp64 16x16 solve (redundant) ----
        for (int r = warp; r < 33; r += TPB / 32) {
            float sum = 0.f;
            for (int b2 = lane; b2 < NBLK; b2 += 32) sum += g_part[r][b2];
            sum = warpSum(sum);
            if (lane == 0) smu[r] = sum;
        }
        __syncthreads();
        if (t < 33) {
            double vv;
            if (t < 2) vv = (double)smu[t];
            else       vv = 2.0 * (double)smu[t] - (double)smu[t & 1];
            mu[t] = vv;
        }
        __syncthreads();
        for (int idx = t; idx < 289; idx += TPB) {
            int a = idx / 17, b2 = idx % 17;
            int d = a - b2; if (d < 0) d = -d;
            M[a][b2] = 0.5 * (mu[a + b2] + mu[d]);
        }
        __syncthreads();
        for (int idx = t; idx < 272; idx += TPB) {
            int r = idx / 16, b2 = idx % 16;
            double w = 4.3 * M[r][b2];
            w += (b2 == 0) ? 4.0 * M[r][1] : 2.0 * (M[r][b2 + 1] + M[r][b2 - 1]);
            W[r][b2] = w;
        }
        __syncthreads();
        {
            int a = t >> 4, b2 = t & 15;
            double g = 4.3 * W[a][b2];
            g += (a == 0) ? 4.0 * W[1][b2] : 2.0 * (W[a + 1][b2] + W[a - 1][b2]);
            G[a][b2] = g;
        }
        if (t < 16) {
            double r = 4.3 * M[t][0];
            r += (t == 0) ? 4.0 * M[1][0] : 2.0 * (M[t + 1][0] + M[t - 1][0]);
            rhs[t] = r;
        }
        __syncthreads();
        if (t == 0) {
            double tr = 0.0;
            for (int k = 0; k < 16; k++) tr += G[k][k];
            double ridge = 1e-12 + 1e-10 * (tr / 16.0);
            for (int k = 0; k < 16; k++) G[k][k] += ridge;
        }
        __syncthreads();
        for (int pp = 0; pp < 16; pp++) {
            if (t > pp && t < 16) sf[t] = G[t][pp] / G[pp][pp];
            __syncthreads();
            int r = t >> 4, cc = t & 15;
            if (r > pp && cc > pp) G[r][cc] -= sf[r] * G[pp][cc];
            if (t > pp && t < 16) rhs[t] -= sf[t] * rhs[pp];
            __syncthreads();
        }
        if (t == 0) {
            for (int pp = 15; pp >= 0; pp--) {
                double su = rhs[pp];
                for (int cc = pp + 1; cc < 16; cc++) su -= G[pp][cc] * rhs[cc];
                rhs[pp] = su / G[pp][pp];
            }
        }
        __syncthreads();
        if (t < 16) cs[t] = (float)rhs[t];
        if (t < 17) {
            double dv;
            if (t == 0)       dv = 4.3 * rhs[0] + 2.0 * rhs[1];
            else if (t == 1)  dv = 4.3 * rhs[1] + 4.0 * rhs[0] + 2.0 * rhs[2];
            else if (t <= 14) dv = 4.3 * rhs[t] + 2.0 * rhs[t - 1] + 2.0 * rhs[t + 1];
            else if (t == 15) dv = 4.3 * rhs[15] + 2.0 * rhs[14];
            else              dv = 2.0 * rhs[15];
            ds[t] = (float)dv;
        }
        __syncthreads();

        if (c == NCYC - 1) {
            // ---- final: x += sum c_k s_k, emit ----
#pragma unroll 2
            for (int kk = 0; kk < 15; kk++) {
                float y = cs[kk];
#pragma unroll
                for (int k = 0; k < 4; k++) {
                    float4 vv = g_S[kk][I4(k)];
                    x[k].x += y * vv.x; x[k].y += y * vv.y;
                    x[k].z += y * vv.z; x[k].w += y * vv.w;
                }
            }
            float y15 = cs[15];
#pragma unroll
            for (int k = 0; k < 4; k++) {
                x[k].x += y15 * p[k].x; x[k].y += y15 * p[k].y;
                x[k].z += y15 * p[k].z; x[k].w += y15 * p[k].w;
                out[I4(k)] = x[k];
            }
        } else {
            // ---- fused x update + analytic residual ----
            float4 racc[4];
#pragma unroll
            for (int k = 0; k < 4; k++) { racc[k].x = racc[k].y = racc[k].z = racc[k].w = 0.f; }
#pragma unroll 2
            for (int kk = 0; kk < 15; kk++) {
                float y = cs[kk];
                float e = (kk == 0) ? (1.0f - ds[0]) : -ds[kk];
#pragma unroll
                for (int k = 0; k < 4; k++) {
                    float4 vv = g_S[kk][I4(k)];
                    x[k].x += y * vv.x;    x[k].y += y * vv.y;
                    x[k].z += y * vv.z;    x[k].w += y * vv.w;
                    racc[k].x += e * vv.x; racc[k].y += e * vv.y;
                    racc[k].z += e * vv.z; racc[k].w += e * vv.w;
                }
            }
            float y15 = cs[15], d15 = ds[15], d16 = ds[16];
#pragma unroll
            for (int k = 0; k < 4; k++) {
                x[k].x += y15 * p[k].x;  x[k].y += y15 * p[k].y;
                x[k].z += y15 * p[k].z;  x[k].w += y15 * p[k].w;
                racc[k].x -= d15 * p[k].x + d16 * s[k].x;
                racc[k].y -= d15 * p[k].y + d16 * s[k].y;
                racc[k].z -= d15 * p[k].z + d16 * s[k].z;
                racc[k].w -= d15 * p[k].w + d16 * s[k].w;
                s[k] = racc[k];
                g_S[0][I4(k)] = racc[k];
            }
            barArrive(); barWait();
        }
    }
}

// ---------------- host orchestration ----------------------------------------
extern "C" void kernel_launch(void* const* d_in, const int* in_sizes, int n_in,
                              void* d_out, int out_size) {
    (void)in_sizes; (void)n_in; (void)out_size;
    const float4* src   = (const float4*)d_in[0];
    const float4* guess = (const float4*)d_in[1];
    float4* out = (float4*)d_out;

    k_all<<<NBLK, TPB>>>(src, guess, out);
}